// round 1
// baseline (speedup 1.0000x reference)
#include <cuda_runtime.h>

// IndRNN: h_t = relu(x_t + w * h_{t-1}), independent per channel c = b*H + h.
// x: (T, B, H) f32, h0: (B, H) f32, w: (H,) f32, out: (T, B, H) f32.
//
// One thread per channel. Software-pipelined register double buffer of depth U
// to keep ~16 outstanding 4B loads per thread (MLP to cover DRAM latency).
// Streaming cache hints: data is touched exactly once.

static constexpr int T  = 2048;
static constexpr int B  = 32;
static constexpr int H  = 1024;
static constexpr int BH = B * H;      // 32768 channels
static constexpr int U  = 16;         // pipeline depth (T % U == 0)

__global__ __launch_bounds__(256, 8)
void indrnn_scan_kernel(const float* __restrict__ x,
                        const float* __restrict__ h0,
                        const float* __restrict__ w,
                        float* __restrict__ out)
{
    const int c = blockIdx.x * blockDim.x + threadIdx.x;   // channel id
    if (c >= BH) return;

    const float wc = __ldg(&w[c & (H - 1)]);
    float h        = __ldg(&h0[c]);

    const float* xp = x   + c;
    float*       op = out + c;

    float buf[U];
    // Prime the pipeline: first U time steps.
#pragma unroll
    for (int i = 0; i < U; i++)
        buf[i] = __ldcs(xp + i * BH);

    for (int t0 = 0; t0 < T; t0 += U) {
        float nbuf[U];
        if (t0 + U < T) {
            // Issue the next chunk's loads before touching the h-chain so all
            // U loads are in flight while we burn the dependent FFMA chain.
#pragma unroll
            for (int i = 0; i < U; i++)
                nbuf[i] = __ldcs(xp + (U + i) * BH);
        }

#pragma unroll
        for (int i = 0; i < U; i++) {
            h = fmaxf(fmaf(wc, h, buf[i]), 0.0f);
            __stcs(op + i * BH, h);
        }

        xp += U * BH;
        op += U * BH;
#pragma unroll
        for (int i = 0; i < U; i++)
            buf[i] = nbuf[i];
    }
}

extern "C" void kernel_launch(void* const* d_in, const int* in_sizes, int n_in,
                              void* d_out, int out_size)
{
    const float* x  = (const float*)d_in[0];   // t_input (T, B, H)
    const float* h0 = (const float*)d_in[1];   // h0      (B, H)
    const float* w  = (const float*)d_in[2];   // weight  (H,)
    float* out      = (float*)d_out;           // (T, B, H)

    const int threads = 256;
    const int blocks  = BH / threads;          // 128
    indrnn_scan_kernel<<<blocks, threads>>>(x, h0, w, out);
}

// round 3
// speedup vs baseline: 2.4568x; 2.4568x over previous
#include <cuda_runtime.h>
#include <math_constants.h>

// IndRNN h_t = relu(x_t + w*h_{t-1}), w >= 0.
// Chunked-scan decomposition: over a chunk, h_out = max(M, A + w^L * h_in),
//   M' = max(0, x + w*M)  (init -inf for w>0, 0 for w==0),
//   A' = x + w*A          (init 0).
// 3 kernels: per-chunk summaries -> sequential combine -> parallel emit.

static constexpr int T  = 2048;
static constexpr int B  = 32;
static constexpr int H  = 1024;
static constexpr int BH = B * H;          // 32768 = 2^15
static constexpr int K  = 32;             // time chunks
static constexpr int L  = T / K;          // 64 steps per chunk
static constexpr int U  = 8;              // load pipeline depth (L % U == 0)

__device__ float g_M[K * BH];
__device__ float g_A[K * BH];
__device__ float g_Hin[K * BH];

// ---------------- Kernel 1: per-chunk (M, A) summaries ----------------
__global__ __launch_bounds__(256)
void k_summary(const float* __restrict__ x, const float* __restrict__ w)
{
    const int gid = blockIdx.x * 256 + threadIdx.x;   // 0 .. K*BH-1
    const int c   = gid & (BH - 1);
    const int k   = gid >> 15;

    const float wc = __ldg(&w[c & (H - 1)]);
    float M = (wc > 0.0f) ? -CUDART_INF_F : 0.0f;     // avoids 0*inf NaN
    float A = 0.0f;

    const float* xp = x + (size_t)k * L * BH + c;

    float buf[U];
#pragma unroll
    for (int i = 0; i < U; i++) buf[i] = xp[i * BH];

    for (int t0 = 0; t0 < L; t0 += U) {
        float nbuf[U];
        if (t0 + U < L) {
#pragma unroll
            for (int i = 0; i < U; i++) nbuf[i] = xp[(U + i) * BH];
        }
#pragma unroll
        for (int i = 0; i < U; i++) {
            M = fmaxf(0.0f, fmaf(wc, M, buf[i]));
            A = fmaf(wc, A, buf[i]);
        }
        xp += U * BH;
        if (t0 + U < L) {
#pragma unroll
            for (int i = 0; i < U; i++) buf[i] = nbuf[i];
        }
    }
    g_M[gid] = M;
    g_A[gid] = A;
}

// ---------------- Kernel 2: sequential combine over chunks ----------------
__global__ __launch_bounds__(256)
void k_combine(const float* __restrict__ h0, const float* __restrict__ w)
{
    const int c = blockIdx.x * 256 + threadIdx.x;     // 0 .. BH-1
    const float wc = __ldg(&w[c & (H - 1)]);

    float wL = wc;                                    // wc^64 = 6 squarings
#pragma unroll
    for (int i = 0; i < 6; i++) wL *= wL;

    float h = __ldg(&h0[c]);
#pragma unroll
    for (int k = 0; k < K; k++) {
        g_Hin[k * BH + c] = h;
        const float M = g_M[k * BH + c];
        const float A = g_A[k * BH + c];
        h = fmaxf(M, fmaf(wL, h, A));
    }
}

// ---------------- Kernel 3: parallel emit (exact recursion per chunk) ----------------
__global__ __launch_bounds__(256)
void k_emit(const float* __restrict__ x, const float* __restrict__ w,
            float* __restrict__ out)
{
    const int gid = blockIdx.x * 256 + threadIdx.x;
    const int c   = gid & (BH - 1);
    const int k   = gid >> 15;

    const float wc = __ldg(&w[c & (H - 1)]);
    float h = g_Hin[gid];                             // gid == k*BH + c

    const float* xp = x   + (size_t)k * L * BH + c;
    float*       op = out + (size_t)k * L * BH + c;

    float buf[U];
#pragma unroll
    for (int i = 0; i < U; i++) buf[i] = xp[i * BH];

    for (int t0 = 0; t0 < L; t0 += U) {
        float nbuf[U];
        if (t0 + U < L) {
#pragma unroll
            for (int i = 0; i < U; i++) nbuf[i] = xp[(U + i) * BH];
        }
#pragma unroll
        for (int i = 0; i < U; i++) {
            h = fmaxf(0.0f, fmaf(wc, h, buf[i]));
            __stcs(op + i * BH, h);
        }
        xp += U * BH;
        op += U * BH;
        if (t0 + U < L) {
#pragma unroll
            for (int i = 0; i < U; i++) buf[i] = nbuf[i];
        }
    }
}

extern "C" void kernel_launch(void* const* d_in, const int* in_sizes, int n_in,
                              void* d_out, int out_size)
{
    const float* x  = (const float*)d_in[0];   // (T, B, H)
    const float* h0 = (const float*)d_in[1];   // (B, H)
    const float* w  = (const float*)d_in[2];   // (H,)
    float* out      = (float*)d_out;

    k_summary<<<K * BH / 256, 256>>>(x, w);
    k_combine<<<BH / 256, 256>>>(h0, w);
    k_emit<<<K * BH / 256, 256>>>(x, w, out);
}